// round 4
// baseline (speedup 1.0000x reference)
#include <cuda_runtime.h>

#define K 512
#define TT 64
#define NB 2
#define NWARP 16
#define NTHREAD 512
#define LOG2E 1.4426950408889634f

// Scratch (allocation-free rule: __device__ globals)
__device__ float g_coeff2[K * K];   // coeff * log2(e)
__device__ float g_bias2[K * K];    // bias  * log2(e)
__device__ float g_em0[K];          // emission softmax col 0
__device__ float g_ed[K];           // emission[.,1] - emission[.,0]
__device__ float g_prior[K];        // softmax(prior_w)

__device__ __forceinline__ float ex2f(float x) {
    float y;
    asm("ex2.approx.ftz.f32 %0, %1;" : "=f"(y) : "f"(x));
    return y;
}

__device__ __forceinline__ float warpSum(float v) {
#pragma unroll
    for (int o = 16; o > 0; o >>= 1) v += __shfl_xor_sync(0xffffffffu, v, o);
    return v;
}

// ---------------- prolog 1: scale coeff/bias by log2(e) ----------------
__global__ void scale_kernel(const float* __restrict__ coeff,
                             const float* __restrict__ bias) {
    int i = blockIdx.x * blockDim.x + threadIdx.x;
    if (i < K * K) {
        g_coeff2[i] = coeff[i] * LOG2E;
        g_bias2[i]  = bias[i]  * LOG2E;
    }
}

// ---------------- prolog 2: emission + prior softmax ----------------
__global__ void prep_kernel(const float* __restrict__ prior_w,
                            const float* __restrict__ emission_w) {
    __shared__ float s_red[NWARP];
    __shared__ float s_scalar;
    int tid = threadIdx.x;
    int lane = tid & 31, wid = tid >> 5;

    // emission row softmax [K,2]
    float w0 = emission_w[tid * 2 + 0];
    float w1 = emission_w[tid * 2 + 1];
    float m = fmaxf(w0, w1);
    float e0 = __expf(w0 - m), e1 = __expf(w1 - m);
    float inv = __fdividef(1.0f, e0 + e1);
    float em0 = e0 * inv, em1 = e1 * inv;
    g_em0[tid] = em0;
    g_ed[tid]  = em1 - em0;

    // prior softmax
    float v = prior_w[tid];
    // block max
    float mx = v;
#pragma unroll
    for (int o = 16; o > 0; o >>= 1) mx = fmaxf(mx, __shfl_xor_sync(0xffffffffu, mx, o));
    if (lane == 0) s_red[wid] = mx;
    __syncthreads();
    if (wid == 0) {
        float u = (lane < NWARP) ? s_red[lane] : -1e30f;
#pragma unroll
        for (int o = 8; o > 0; o >>= 1) u = fmaxf(u, __shfl_xor_sync(0xffffffffu, u, o));
        if (lane == 0) s_scalar = u;
    }
    __syncthreads();
    float pm = s_scalar;
    float pe = __expf(v - pm);
    __syncthreads();
    float ws = warpSum(pe);
    if (lane == 0) s_red[wid] = ws;
    __syncthreads();
    if (wid == 0) {
        float u = (lane < NWARP) ? s_red[lane] : 0.0f;
#pragma unroll
        for (int o = 8; o > 0; o >>= 1) u += __shfl_xor_sync(0xffffffffu, u, o);
        if (lane == 0) s_scalar = u;
    }
    __syncthreads();
    g_prior[tid] = __fdividef(pe, s_scalar);
}

// ---------------- main persistent HMM kernel ----------------
__global__ void __launch_bounds__(NTHREAD, 1)
hmm_main(const float* __restrict__ x, float* __restrict__ out) {
    __shared__ float s_post[NB][K];          // 4 KB
    __shared__ float s_buf[NWARP * K];       // 32 KB: per-warp pbe partials
    __shared__ float s_em0[K];               // 2 KB
    __shared__ float s_ed[K];                // 2 KB
    __shared__ float s_x[NB][TT];            // 512 B
    __shared__ float s_red[NWARP];
    __shared__ float s_S;

    const int tid = threadIdx.x;
    const int lane = tid & 31;
    const int wid = tid >> 5;
    const int b0 = blockIdx.x * NB;

    s_em0[tid] = g_em0[tid];
    s_ed[tid]  = g_ed[tid];
    if (tid < NB * TT) {
        int b = tid / TT, t = tid % TT;
        s_x[b][t] = x[(b0 + b) * TT + t];
    }
    __syncthreads();

    // ---- init: post0 = evidence(prior, x[:,0]) ----
#pragma unroll
    for (int b = 0; b < NB; b++) {
        float xt = s_x[b][0];
        float p = g_prior[tid] * fmaf(xt, s_ed[tid], s_em0[tid]);
        float v = warpSum(p);
        if (lane == 0) s_red[wid] = v;
        __syncthreads();
        if (wid == 0) {
            float u = (lane < NWARP) ? s_red[lane] : 0.0f;
#pragma unroll
            for (int o = 8; o > 0; o >>= 1) u += __shfl_xor_sync(0xffffffffu, u, o);
            if (lane == 0) s_S = u;
        }
        __syncthreads();
        s_post[b][tid] = __fdividef(p, s_S);
        __syncthreads();
    }

    const int rows_per_warp = K / NWARP;     // 32

    for (int t = 1; t < TT; t++) {
        float acc0[16], acc1[16];
#pragma unroll
        for (int i = 0; i < 16; i++) { acc0[i] = 0.0f; acc1[i] = 0.0f; }

        // ---- phase 1: per-warp rows, accumulate pbe partials in regs ----
        for (int r = 0; r < rows_per_warp; r++) {
            int j = wid * rows_per_warp + r;
            const float4* crow = reinterpret_cast<const float4*>(g_coeff2 + j * K);
            const float4* brow = reinterpret_cast<const float4*>(g_bias2 + j * K);

            float cc[16], dd[16];
#pragma unroll
            for (int i = 0; i < 4; i++) {
                float4 c = crow[i * 32 + lane];
                float4 d = brow[i * 32 + lane];
                cc[i * 4 + 0] = c.x; cc[i * 4 + 1] = c.y; cc[i * 4 + 2] = c.z; cc[i * 4 + 3] = c.w;
                dd[i * 4 + 0] = d.x; dd[i * 4 + 1] = d.y; dd[i * 4 + 2] = d.z; dd[i * 4 + 3] = d.w;
            }
            float pj0 = s_post[0][j];
            float pj1 = s_post[1][j];

            // batch 0
            {
                float e[16]; float ls = 0.0f;
#pragma unroll
                for (int i = 0; i < 16; i++) {
                    e[i] = ex2f(fmaf(pj0, cc[i], dd[i]));
                    ls += e[i];
                }
                float Z = warpSum(ls);
                float w = __fdividef(pj0, Z);
#pragma unroll
                for (int i = 0; i < 16; i++) acc0[i] = fmaf(w, e[i], acc0[i]);
            }
            // batch 1
            {
                float e[16]; float ls = 0.0f;
#pragma unroll
                for (int i = 0; i < 16; i++) {
                    e[i] = ex2f(fmaf(pj1, cc[i], dd[i]));
                    ls += e[i];
                }
                float Z = warpSum(ls);
                float w = __fdividef(pj1, Z);
#pragma unroll
                for (int i = 0; i < 16; i++) acc1[i] = fmaf(w, e[i], acc1[i]);
            }
        }
        __syncthreads();   // A: all warps done reading s_post / s_buf from prior step

        // ---- phase 2, batch 0: cross-warp reduce + evidence ----
        {
            float4* bw = reinterpret_cast<float4*>(s_buf + wid * K);
#pragma unroll
            for (int i = 0; i < 4; i++)
                bw[i * 32 + lane] = make_float4(acc0[i * 4 + 0], acc0[i * 4 + 1],
                                                acc0[i * 4 + 2], acc0[i * 4 + 3]);
            __syncthreads();   // B
            float pbe = 0.0f;
#pragma unroll
            for (int w = 0; w < NWARP; w++) pbe += s_buf[w * K + tid];
            float xt = s_x[0][t];
            float p = pbe * fmaf(xt, s_ed[tid], s_em0[tid]);
            float v = warpSum(p);
            if (lane == 0) s_red[wid] = v;
            __syncthreads();
            if (wid == 0) {
                float u = (lane < NWARP) ? s_red[lane] : 0.0f;
#pragma unroll
                for (int o = 8; o > 0; o >>= 1) u += __shfl_xor_sync(0xffffffffu, u, o);
                if (lane == 0) s_S = u;
            }
            __syncthreads();
            s_post[0][tid] = __fdividef(p, s_S);
            __syncthreads();   // C: s_buf reads done, safe to overwrite
        }

        // ---- phase 2, batch 1 ----
        {
            float4* bw = reinterpret_cast<float4*>(s_buf + wid * K);
#pragma unroll
            for (int i = 0; i < 4; i++)
                bw[i * 32 + lane] = make_float4(acc1[i * 4 + 0], acc1[i * 4 + 1],
                                                acc1[i * 4 + 2], acc1[i * 4 + 3]);
            __syncthreads();   // D
            float pbe = 0.0f;
#pragma unroll
            for (int w = 0; w < NWARP; w++) pbe += s_buf[w * K + tid];
            float xt = s_x[1][t];
            float p = pbe * fmaf(xt, s_ed[tid], s_em0[tid]);
            float v = warpSum(p);
            if (lane == 0) s_red[wid] = v;
            __syncthreads();
            if (wid == 0) {
                float u = (lane < NWARP) ? s_red[lane] : 0.0f;
#pragma unroll
                for (int o = 8; o > 0; o >>= 1) u += __shfl_xor_sync(0xffffffffu, u, o);
                if (lane == 0) s_S = u;
            }
            __syncthreads();
            s_post[1][tid] = __fdividef(p, s_S);
            __syncthreads();   // E: before next step's phase 1 reads s_post
        }
    }

    out[(b0 + 0) * K + tid] = s_post[0][tid];
    out[(b0 + 1) * K + tid] = s_post[1][tid];
}

extern "C" void kernel_launch(void* const* d_in, const int* in_sizes, int n_in,
                              void* d_out, int out_size) {
    const float* x          = (const float*)d_in[0];   // [B, T] = [256, 64]
    const float* prior_w    = (const float*)d_in[1];   // [K]
    const float* emission_w = (const float*)d_in[2];   // [K, 2]
    const float* coeff      = (const float*)d_in[3];   // [K, K]
    const float* bias       = (const float*)d_in[4];   // [K, K]
    float* out = (float*)d_out;                        // [B, K]

    scale_kernel<<<(K * K + NTHREAD - 1) / NTHREAD, NTHREAD>>>(coeff, bias);
    prep_kernel<<<1, NTHREAD>>>(prior_w, emission_w);
    hmm_main<<<256 / NB, NTHREAD>>>(x, out);
}

// round 5
// speedup vs baseline: 1.1025x; 1.1025x over previous
#include <cuda_runtime.h>
#include <cuda_fp16.h>

#define K 512
#define TT 64
#define NB 2
#define NWARP 16
#define NTHREAD 512
#define LOG2E 1.4426950408889634f
#define YSHIFT 4.0f   // folded into stored bias; cancels exactly in e/Z

// Scratch (allocation-free rule: __device__ globals)
__device__ __align__(16) __half g_ch[K * K];   // coeff * log2(e)  (fp16)
__device__ __align__(16) __half g_bh[K * K];   // bias * log2(e) - YSHIFT (fp16)
__device__ float g_em0[K];          // emission softmax col 0
__device__ float g_ed[K];           // emission[.,1] - emission[.,0]
__device__ float g_prior[K];        // softmax(prior_w)

__device__ __forceinline__ unsigned h2ex2(unsigned x) {
    unsigned y;
    asm("ex2.approx.f16x2 %0, %1;" : "=r"(y) : "r"(x));
    return y;
}

__device__ __forceinline__ float warpSum(float v) {
#pragma unroll
    for (int o = 16; o > 0; o >>= 1) v += __shfl_xor_sync(0xffffffffu, v, o);
    return v;
}

// ---------------- prolog 1: scale + convert to fp16 ----------------
__global__ void scale_kernel(const float* __restrict__ coeff,
                             const float* __restrict__ bias) {
    int i = blockIdx.x * blockDim.x + threadIdx.x;
    if (i < K * K) {
        g_ch[i] = __float2half_rn(coeff[i] * LOG2E);
        g_bh[i] = __float2half_rn(bias[i] * LOG2E - YSHIFT);
    }
}

// ---------------- prolog 2: emission + prior softmax ----------------
__global__ void prep_kernel(const float* __restrict__ prior_w,
                            const float* __restrict__ emission_w) {
    __shared__ float s_red[NWARP];
    __shared__ float s_scalar;
    int tid = threadIdx.x;
    int lane = tid & 31, wid = tid >> 5;

    // emission row softmax [K,2]
    float w0 = emission_w[tid * 2 + 0];
    float w1 = emission_w[tid * 2 + 1];
    float m = fmaxf(w0, w1);
    float e0 = __expf(w0 - m), e1 = __expf(w1 - m);
    float inv = __fdividef(1.0f, e0 + e1);
    float em0 = e0 * inv, em1 = e1 * inv;
    g_em0[tid] = em0;
    g_ed[tid]  = em1 - em0;

    // prior softmax
    float v = prior_w[tid];
    float mx = v;
#pragma unroll
    for (int o = 16; o > 0; o >>= 1) mx = fmaxf(mx, __shfl_xor_sync(0xffffffffu, mx, o));
    if (lane == 0) s_red[wid] = mx;
    __syncthreads();
    if (wid == 0) {
        float u = (lane < NWARP) ? s_red[lane] : -1e30f;
#pragma unroll
        for (int o = 8; o > 0; o >>= 1) u = fmaxf(u, __shfl_xor_sync(0xffffffffu, u, o));
        if (lane == 0) s_scalar = u;
    }
    __syncthreads();
    float pm = s_scalar;
    float pe = __expf(v - pm);
    __syncthreads();
    float ws = warpSum(pe);
    if (lane == 0) s_red[wid] = ws;
    __syncthreads();
    if (wid == 0) {
        float u = (lane < NWARP) ? s_red[lane] : 0.0f;
#pragma unroll
        for (int o = 8; o > 0; o >>= 1) u += __shfl_xor_sync(0xffffffffu, u, o);
        if (lane == 0) s_scalar = u;
    }
    __syncthreads();
    g_prior[tid] = __fdividef(pe, s_scalar);
}

// ---------------- main persistent HMM kernel ----------------
__global__ void __launch_bounds__(NTHREAD, 1)
hmm_main(const float* __restrict__ x, float* __restrict__ out) {
    __shared__ float s_post[NB][K];          // 4 KB
    __shared__ float s_buf[NWARP * K];       // 32 KB: per-warp pbe partials
    __shared__ float s_em0[K];               // 2 KB
    __shared__ float s_ed[K];                // 2 KB
    __shared__ float s_x[NB][TT];            // 512 B
    __shared__ float s_red[NWARP];
    __shared__ float s_S;

    const int tid = threadIdx.x;
    const int lane = tid & 31;
    const int wid = tid >> 5;
    const int b0 = blockIdx.x * NB;

    s_em0[tid] = g_em0[tid];
    s_ed[tid]  = g_ed[tid];
    if (tid < NB * TT) {
        int b = tid / TT, t = tid % TT;
        s_x[b][t] = x[(b0 + b) * TT + t];
    }
    __syncthreads();

    // ---- init: post0 = evidence(prior, x[:,0]) ----
#pragma unroll
    for (int b = 0; b < NB; b++) {
        float xt = s_x[b][0];
        float p = g_prior[tid] * fmaf(xt, s_ed[tid], s_em0[tid]);
        float v = warpSum(p);
        if (lane == 0) s_red[wid] = v;
        __syncthreads();
        if (wid == 0) {
            float u = (lane < NWARP) ? s_red[lane] : 0.0f;
#pragma unroll
            for (int o = 8; o > 0; o >>= 1) u += __shfl_xor_sync(0xffffffffu, u, o);
            if (lane == 0) s_S = u;
        }
        __syncthreads();
        s_post[b][tid] = __fdividef(p, s_S);
        __syncthreads();
    }

    const int rows_per_warp = K / NWARP;     // 32

    for (int t = 1; t < TT; t++) {
        float acc0[16], acc1[16];
#pragma unroll
        for (int i = 0; i < 16; i++) { acc0[i] = 0.0f; acc1[i] = 0.0f; }

        // ---- phase 1: per-warp rows, accumulate pbe partials in regs ----
        // k mapping per lane: e[i] -> k = (i<8 ? lane*8+i : 256 + lane*8 + (i-8))
        for (int r = 0; r < rows_per_warp; r++) {
            int j = wid * rows_per_warp + r;
            const uint4* crow = reinterpret_cast<const uint4*>(g_ch + j * K);
            const uint4* brow = reinterpret_cast<const uint4*>(g_bh + j * K);

            union { uint4 u[2]; unsigned h2[8]; } C, Bv;
            C.u[0]  = crow[lane];       C.u[1]  = crow[32 + lane];
            Bv.u[0] = brow[lane];       Bv.u[1] = brow[32 + lane];

            float pj0 = s_post[0][j];
            float pj1 = s_post[1][j];

            // batch 0
            {
                __half2 p2 = __float2half2_rn(pj0);
                unsigned p2u = *reinterpret_cast<unsigned*>(&p2);
                float e[16];
                __half2 ls2 = __float2half2_rn(0.0f);
#pragma unroll
                for (int i = 0; i < 8; i++) {
                    __half2 c2 = *reinterpret_cast<const __half2*>(&C.h2[i]);
                    __half2 b2 = *reinterpret_cast<const __half2*>(&Bv.h2[i]);
                    __half2 y  = __hfma2(*reinterpret_cast<__half2*>(&p2u), c2, b2);
                    unsigned eu = h2ex2(*reinterpret_cast<unsigned*>(&y));
                    __half2 ev = *reinterpret_cast<__half2*>(&eu);
                    ls2 = __hadd2(ls2, ev);
                    float2 ef = __half22float2(ev);
                    e[2 * i]     = ef.x;
                    e[2 * i + 1] = ef.y;
                }
                float Z = warpSum(__low2float(ls2) + __high2float(ls2));
                float w = __fdividef(pj0, Z);
#pragma unroll
                for (int i = 0; i < 16; i++) acc0[i] = fmaf(w, e[i], acc0[i]);
            }
            // batch 1
            {
                __half2 p2 = __float2half2_rn(pj1);
                unsigned p2u = *reinterpret_cast<unsigned*>(&p2);
                float e[16];
                __half2 ls2 = __float2half2_rn(0.0f);
#pragma unroll
                for (int i = 0; i < 8; i++) {
                    __half2 c2 = *reinterpret_cast<const __half2*>(&C.h2[i]);
                    __half2 b2 = *reinterpret_cast<const __half2*>(&Bv.h2[i]);
                    __half2 y  = __hfma2(*reinterpret_cast<__half2*>(&p2u), c2, b2);
                    unsigned eu = h2ex2(*reinterpret_cast<unsigned*>(&y));
                    __half2 ev = *reinterpret_cast<__half2*>(&eu);
                    ls2 = __hadd2(ls2, ev);
                    float2 ef = __half22float2(ev);
                    e[2 * i]     = ef.x;
                    e[2 * i + 1] = ef.y;
                }
                float Z = warpSum(__low2float(ls2) + __high2float(ls2));
                float w = __fdividef(pj1, Z);
#pragma unroll
                for (int i = 0; i < 16; i++) acc1[i] = fmaf(w, e[i], acc1[i]);
            }
        }
        __syncthreads();   // A: all warps done reading s_post from prior step

        // ---- phase 2, batch 0: cross-warp reduce + evidence ----
        {
            // write acc partials at the k-mapping used in phase 1
            float* bw = s_buf + wid * K;
#pragma unroll
            for (int u = 0; u < 2; u++) {
                int kbase = u * 256 + lane * 8;
                float4 v0 = make_float4(acc0[u * 8 + 0], acc0[u * 8 + 1],
                                        acc0[u * 8 + 2], acc0[u * 8 + 3]);
                float4 v1 = make_float4(acc0[u * 8 + 4], acc0[u * 8 + 5],
                                        acc0[u * 8 + 6], acc0[u * 8 + 7]);
                *reinterpret_cast<float4*>(bw + kbase)     = v0;
                *reinterpret_cast<float4*>(bw + kbase + 4) = v1;
            }
            __syncthreads();   // B
            float pbe = 0.0f;
#pragma unroll
            for (int w = 0; w < NWARP; w++) pbe += s_buf[w * K + tid];
            float xt = s_x[0][t];
            float p = pbe * fmaf(xt, s_ed[tid], s_em0[tid]);
            float v = warpSum(p);
            if (lane == 0) s_red[wid] = v;
            __syncthreads();
            if (wid == 0) {
                float u = (lane < NWARP) ? s_red[lane] : 0.0f;
#pragma unroll
                for (int o = 8; o > 0; o >>= 1) u += __shfl_xor_sync(0xffffffffu, u, o);
                if (lane == 0) s_S = u;
            }
            __syncthreads();
            s_post[0][tid] = __fdividef(p, s_S);
            __syncthreads();   // C: s_buf reads done, safe to overwrite
        }

        // ---- phase 2, batch 1 ----
        {
            float* bw = s_buf + wid * K;
#pragma unroll
            for (int u = 0; u < 2; u++) {
                int kbase = u * 256 + lane * 8;
                float4 v0 = make_float4(acc1[u * 8 + 0], acc1[u * 8 + 1],
                                        acc1[u * 8 + 2], acc1[u * 8 + 3]);
                float4 v1 = make_float4(acc1[u * 8 + 4], acc1[u * 8 + 5],
                                        acc1[u * 8 + 6], acc1[u * 8 + 7]);
                *reinterpret_cast<float4*>(bw + kbase)     = v0;
                *reinterpret_cast<float4*>(bw + kbase + 4) = v1;
            }
            __syncthreads();   // D
            float pbe = 0.0f;
#pragma unroll
            for (int w = 0; w < NWARP; w++) pbe += s_buf[w * K + tid];
            float xt = s_x[1][t];
            float p = pbe * fmaf(xt, s_ed[tid], s_em0[tid]);
            float v = warpSum(p);
            if (lane == 0) s_red[wid] = v;
            __syncthreads();
            if (wid == 0) {
                float u = (lane < NWARP) ? s_red[lane] : 0.0f;
#pragma unroll
                for (int o = 8; o > 0; o >>= 1) u += __shfl_xor_sync(0xffffffffu, u, o);
                if (lane == 0) s_S = u;
            }
            __syncthreads();
            s_post[1][tid] = __fdividef(p, s_S);
            __syncthreads();   // E: before next step's phase 1 reads s_post
        }
    }

    out[(b0 + 0) * K + tid] = s_post[0][tid];
    out[(b0 + 1) * K + tid] = s_post[1][tid];
}

extern "C" void kernel_launch(void* const* d_in, const int* in_sizes, int n_in,
                              void* d_out, int out_size) {
    const float* x          = (const float*)d_in[0];   // [B, T] = [256, 64]
    const float* prior_w    = (const float*)d_in[1];   // [K]
    const float* emission_w = (const float*)d_in[2];   // [K, 2]
    const float* coeff      = (const float*)d_in[3];   // [K, K]
    const float* bias       = (const float*)d_in[4];   // [K, K]
    float* out = (float*)d_out;                        // [B, K]

    scale_kernel<<<(K * K + NTHREAD - 1) / NTHREAD, NTHREAD>>>(coeff, bias);
    prep_kernel<<<1, NTHREAD>>>(prior_w, emission_w);
    hmm_main<<<256 / NB, NTHREAD>>>(x, out);
}